// round 2
// baseline (speedup 1.0000x reference)
#include <cuda_runtime.h>
#include <float.h>

// Problem constants
#define BATCH   16
#define CDIM    256
#define HW      1024            // 32*32
#define NROWS   16384           // BATCH*HW
#define KCODES  8192
#define NELEM   4194304         // BATCH*CDIM*HW

// GEMM tiling
#define BM      128
#define BN      128
#define BKC     16
#define BNP     136             // padded Bs row (multiple of 4 for float4 reads)

// Scratch (no cudaMalloc allowed)
__device__ int   g_codes[NROWS];
__device__ float g_esq[KCODES];
__device__ float g_zsq[NROWS];
__device__ float g_partial[NELEM / 256];

// ---------------------------------------------------------------------------
// e_sq[k] = sum_c codebook[k][c]^2        (one warp per code)
// ---------------------------------------------------------------------------
__global__ void vq_esq_kernel(const float* __restrict__ cbk) {
    int k    = blockIdx.x * 8 + (threadIdx.x >> 5);
    int lane = threadIdx.x & 31;
    const float4* row = (const float4*)(cbk + (size_t)k * CDIM);
    float s = 0.f;
    #pragma unroll
    for (int i = lane; i < CDIM / 4; i += 32) {
        float4 v = row[i];
        s += v.x * v.x + v.y * v.y + v.z * v.z + v.w * v.w;
    }
    #pragma unroll
    for (int off = 16; off > 0; off >>= 1)
        s += __shfl_down_sync(0xffffffffu, s, off);
    if (lane == 0) g_esq[k] = s;
}

// ---------------------------------------------------------------------------
// z_sq[n] = sum_c z[b][c][hw]^2           (one thread per row, coalesced in hw)
// ---------------------------------------------------------------------------
__global__ void vq_zsq_kernel(const float* __restrict__ z) {
    int n  = blockIdx.x * 256 + threadIdx.x;
    int b  = n >> 10;
    int hw = n & 1023;
    const float* p = z + (size_t)b * CDIM * HW + hw;
    float s = 0.f;
    #pragma unroll 8
    for (int c = 0; c < CDIM; c++) {
        float v = p[(size_t)c * HW];
        s += v * v;
    }
    g_zsq[n] = s;
}

// ---------------------------------------------------------------------------
// Fused GEMM + argmin: per-row argmin_k of (z_sq - 2*cross + e_sq).
// A panel (128 rows x 256 C) resident in SMEM; codes streamed in 128-chunks.
// ---------------------------------------------------------------------------
__global__ __launch_bounds__(256, 1)
void vq_main_kernel(const float* __restrict__ z, const float* __restrict__ cbk,
                    float* __restrict__ out_codes_f) {
    extern __shared__ float sm[];
    float* As   = sm;                                  // 32768 floats (128KB)
    float* Bs   = sm + CDIM * BM;                      // BKC*BNP floats
    float* redv = Bs + BKC * BNP;                      // 128*16 floats
    int*   redi = (int*)(redv + BM * 16);              // 128*16 ints

    const int tid = threadIdx.x;
    const int tx  = tid & 15;
    const int ty  = tid >> 4;
    const int rowbase = blockIdx.x * BM;
    const int b   = rowbase >> 10;
    const int hw0 = rowbase & 1023;

    // Load A panel: As[c*128 + r] = z[b][c][hw0 + r]  (fully coalesced float4)
    {
        const float* zb = z + (size_t)b * CDIM * HW + hw0;
        float4* As4 = (float4*)As;
        for (int idx = tid; idx < CDIM * (BM / 4); idx += 256) {
            int c = idx >> 5;          // BM/4 = 32 float4 per c-row
            int q = idx & 31;
            As4[idx] = *(const float4*)(zb + (size_t)c * HW + q * 4);
        }
    }

    const int r0 = ty * 8;
    float zs[8];
    #pragma unroll
    for (int i = 0; i < 8; i++) zs[i] = g_zsq[rowbase + r0 + i];

    float rmin[8];
    int   ridx[8];
    #pragma unroll
    for (int i = 0; i < 8; i++) { rmin[i] = FLT_MAX; ridx[i] = 0; }

    __syncthreads();

    const float4* cb4 = (const float4*)cbk;

    for (int cb0 = 0; cb0 < KCODES; cb0 += BN) {
        float acc[8][8];
        #pragma unroll
        for (int i = 0; i < 8; i++)
            #pragma unroll
            for (int j = 0; j < 8; j++) acc[i][j] = 0.f;

        for (int kc = 0; kc < CDIM; kc += BKC) {
            __syncthreads();
            // Load + transpose B chunk: Bs[c'][code], c' in [0,16), code in [0,128)
            for (int idx = tid; idx < 512; idx += 256) {
                int code = idx >> 2;
                int cq   = idx & 3;
                float4 v = cb4[(size_t)(cb0 + code) * (CDIM / 4) + (kc >> 2) + cq];
                int c0 = cq * 4;
                Bs[(c0 + 0) * BNP + code] = v.x;
                Bs[(c0 + 1) * BNP + code] = v.y;
                Bs[(c0 + 2) * BNP + code] = v.z;
                Bs[(c0 + 3) * BNP + code] = v.w;
            }
            __syncthreads();

            #pragma unroll 4
            for (int k = 0; k < BKC; k++) {
                const float4* arow = (const float4*)(As + (size_t)(kc + k) * BM);
                float4 a0 = arow[ty * 2];
                float4 a1 = arow[ty * 2 + 1];
                float4 b0 = *(const float4*)(Bs + k * BNP + tx * 8);
                float4 b1 = *(const float4*)(Bs + k * BNP + tx * 8 + 4);
                float av[8] = {a0.x, a0.y, a0.z, a0.w, a1.x, a1.y, a1.z, a1.w};
                float bv[8] = {b0.x, b0.y, b0.z, b0.w, b1.x, b1.y, b1.z, b1.w};
                #pragma unroll
                for (int i = 0; i < 8; i++)
                    #pragma unroll
                    for (int j = 0; j < 8; j++)
                        acc[i][j] += av[i] * bv[j];
            }
        }

        // Epilogue: distances + running argmin (cols ascend within thread ->
        // strict < reproduces first-index tie-break for this thread's cols)
        #pragma unroll
        for (int j = 0; j < 8; j++) {
            int col  = cb0 + tx * 8 + j;
            float es = g_esq[col];
            #pragma unroll
            for (int i = 0; i < 8; i++) {
                // match reference rounding: (z_sq - 2*cross) + e_sq
                float t = zs[i] - 2.0f * acc[i][j];
                float d = t + es;
                if (d < rmin[i]) { rmin[i] = d; ridx[i] = col; }
            }
        }
    }

    // Cross-thread (tx) reduction per row with first-index tie-break
    __syncthreads();
    #pragma unroll
    for (int i = 0; i < 8; i++) {
        redv[(r0 + i) * 16 + tx] = rmin[i];
        redi[(r0 + i) * 16 + tx] = ridx[i];
    }
    __syncthreads();
    if (tid < BM) {
        int r = tid;
        float best = redv[r * 16];
        int   bi   = redi[r * 16];
        #pragma unroll
        for (int t = 1; t < 16; t++) {
            float v  = redv[r * 16 + t];
            int   ix = redi[r * 16 + t];
            if (v < best || (v == best && ix < bi)) { best = v; bi = ix; }
        }
        g_codes[rowbase + r]      = bi;
        out_codes_f[rowbase + r]  = (float)bi;
    }
}

// ---------------------------------------------------------------------------
// Gather quantized output (straight-through: z + (q - z), exact ref rounding)
// and accumulate per-block partial sums of (q - z)^2.
// ---------------------------------------------------------------------------
__global__ void vq_gather_kernel(const float* __restrict__ z,
                                 const float* __restrict__ cbk,
                                 float* __restrict__ out_q) {
    __shared__ float sred[256];
    int o  = blockIdx.x * 256 + threadIdx.x;
    int hw = o & 1023;
    int c  = (o >> 10) & 255;
    int b  = o >> 18;
    int code = g_codes[(b << 10) + hw];
    float q  = __ldg(&cbk[(size_t)code * CDIM + c]);
    float zv = z[o];
    float qz = q - zv;
    out_q[o] = zv + qz;                 // straight-through numeric path
    sred[threadIdx.x] = qz * qz;
    __syncthreads();
    #pragma unroll
    for (int off = 128; off > 0; off >>= 1) {
        if (threadIdx.x < off) sred[threadIdx.x] += sred[threadIdx.x + off];
        __syncthreads();
    }
    if (threadIdx.x == 0) g_partial[blockIdx.x] = sred[0];
}

// ---------------------------------------------------------------------------
// Deterministic final reduction: vq_loss = 1.25 * mean((q - z)^2)
// ---------------------------------------------------------------------------
__global__ void vq_finalize_kernel(float* __restrict__ out_loss) {
    __shared__ float s[256];
    float a = 0.f;
    for (int i = threadIdx.x; i < NELEM / 256; i += 256) a += g_partial[i];
    s[threadIdx.x] = a;
    __syncthreads();
    #pragma unroll
    for (int off = 128; off > 0; off >>= 1) {
        if (threadIdx.x < off) s[threadIdx.x] += s[threadIdx.x + off];
        __syncthreads();
    }
    if (threadIdx.x == 0)
        out_loss[0] = s[0] * (1.25f / (float)NELEM);
}

// ---------------------------------------------------------------------------
extern "C" void kernel_launch(void* const* d_in, const int* in_sizes, int n_in,
                              void* d_out, int out_size) {
    const float* z   = (const float*)d_in[0];   // (16,256,32,32) f32
    const float* cbk = (const float*)d_in[1];   // (8192,256) f32

    float* out        = (float*)d_out;
    float* out_codes  = out;                     // 16384 floats
    float* out_q      = out + NROWS;             // 4194304 floats
    float* out_loss   = out + NROWS + NELEM;     // 1 float

    const size_t SMEM = (size_t)(CDIM * BM + BKC * BNP + BM * 16) * sizeof(float)
                      + (size_t)(BM * 16) * sizeof(int);
    cudaFuncSetAttribute(vq_main_kernel,
                         cudaFuncAttributeMaxDynamicSharedMemorySize, (int)SMEM);

    vq_esq_kernel<<<KCODES / 8, 256>>>(cbk);
    vq_zsq_kernel<<<NROWS / 256, 256>>>(z);
    vq_main_kernel<<<NROWS / BM, 256, SMEM>>>(z, cbk, out_codes);
    vq_gather_kernel<<<NELEM / 256, 256>>>(z, cbk, out_q);
    vq_finalize_kernel<<<1, 256>>>(out_loss);
}

// round 7
// speedup vs baseline: 1.7470x; 1.7470x over previous
#include <cuda_runtime.h>
#include <float.h>
#include <stdint.h>

// ---------------------------------------------------------------------------
// Problem constants
// ---------------------------------------------------------------------------
#define BATCH   16
#define CDIM    256
#define HW      1024
#define NROWS   16384          // BATCH*HW
#define KCODES  8192
#define NELEM   4194304        // BATCH*CDIM*HW

// GEMM config: tf32 3x split => K = 768 virtual, 24 chunks of 32 floats
#define MTILE       128
#define NTILE       128
#define NCHUNKS     64         // 8192 / 128 n-chunks per row
#define NKCH        24
#define STAGES      4
#define STAGE_BYTES 32768      // A 16K + B 16K
#define B_OFF       16384
#define SMEM_NEED   (STAGES * STAGE_BYTES)   // 128 KB

// ---------------------------------------------------------------------------
// Device scratch (no cudaMalloc allowed)
// ---------------------------------------------------------------------------
__device__ __align__(16) float g_Ahi[NROWS * CDIM];
__device__ __align__(16) float g_Alo[NROWS * CDIM];
__device__ __align__(16) float g_Bhi[KCODES * CDIM];
__device__ __align__(16) float g_Blo[KCODES * CDIM];
__device__ float g_esq[KCODES];
__device__ float g_zsq[NROWS];
__device__ float g_pmin[NROWS * NCHUNKS];
__device__ int   g_pidx[NROWS * NCHUNKS];
__device__ int   g_codes[NROWS];
__device__ float g_partial[NELEM / 256];

// ---------------------------------------------------------------------------
// Helpers
// ---------------------------------------------------------------------------
__device__ __forceinline__ uint32_t smem_u32(const void* p) {
    uint32_t a;
    asm("{ .reg .u64 t; cvta.to.shared.u64 t, %1; cvt.u32.u64 %0, t; }"
        : "=r"(a) : "l"(p));
    return a;
}

__device__ __forceinline__ float to_tf32(float a) {
    float r;
    asm("cvt.rna.tf32.f32 %0, %1;" : "=f"(r) : "f"(a));
    return r;
}

// SW128-style swizzle (relative to tile base; 16B-granular)
#define SWZ(o) ((o) ^ (((o) >> 3) & 0x70))

__device__ __forceinline__ void cp_async16(uint32_t dst, const void* src) {
    asm volatile("cp.async.cg.shared.global [%0], [%1], 16;"
                 :: "r"(dst), "l"(src) : "memory");
}
#define CP_COMMIT() asm volatile("cp.async.commit_group;" ::: "memory")

__device__ __forceinline__ void mma_tf32(float* c, const uint32_t* a,
                                         const uint32_t* b) {
    asm volatile(
        "mma.sync.aligned.m16n8k8.row.col.f32.tf32.tf32.f32 "
        "{%0,%1,%2,%3}, {%4,%5,%6,%7}, {%8,%9}, {%0,%1,%2,%3};"
        : "+f"(c[0]), "+f"(c[1]), "+f"(c[2]), "+f"(c[3])
        : "r"(a[0]), "r"(a[1]), "r"(a[2]), "r"(a[3]), "r"(b[0]), "r"(b[1]));
}

// ---------------------------------------------------------------------------
// e_sq[k] = sum_c codebook[k][c]^2
// ---------------------------------------------------------------------------
__global__ void vq_esq_kernel(const float* __restrict__ cbk) {
    int k    = blockIdx.x * 8 + (threadIdx.x >> 5);
    int lane = threadIdx.x & 31;
    const float4* row = (const float4*)(cbk + (size_t)k * CDIM);
    float s = 0.f;
    #pragma unroll
    for (int i = lane; i < CDIM / 4; i += 32) {
        float4 v = row[i];
        s += v.x * v.x + v.y * v.y + v.z * v.z + v.w * v.w;
    }
    #pragma unroll
    for (int off = 16; off > 0; off >>= 1)
        s += __shfl_down_sync(0xffffffffu, s, off);
    if (lane == 0) g_esq[k] = s;
}

// ---------------------------------------------------------------------------
// z_sq[n] = sum_c z[b][c][hw]^2
// ---------------------------------------------------------------------------
__global__ void vq_zsq_kernel(const float* __restrict__ z) {
    int n  = blockIdx.x * 256 + threadIdx.x;
    int b  = n >> 10;
    int hw = n & 1023;
    const float* p = z + (size_t)b * CDIM * HW + hw;
    float s = 0.f;
    #pragma unroll 8
    for (int c = 0; c < CDIM; c++) {
        float v = p[(size_t)c * HW];
        s += v * v;
    }
    g_zsq[n] = s;
}

// ---------------------------------------------------------------------------
// Split z -> tf32 hi/lo, transposed to row-major (n, c), via SMEM transpose
// ---------------------------------------------------------------------------
__global__ void vq_split_z(const float* __restrict__ z) {
    __shared__ float t[32][33];
    int b   = blockIdx.z;
    int c0  = blockIdx.y * 32;
    int hw0 = blockIdx.x * 32;
    int tx  = threadIdx.x & 31;
    int ty  = threadIdx.x >> 5;        // 0..7
    const float* src = z + ((size_t)b * CDIM + c0) * HW + hw0;
    #pragma unroll
    for (int j = 0; j < 4; j++) {
        int c = ty + j * 8;
        t[c][tx] = src[(size_t)c * HW + tx];
    }
    __syncthreads();
    #pragma unroll
    for (int j = 0; j < 4; j++) {
        int hh = ty + j * 8;
        float a  = t[tx][hh];
        float hi = to_tf32(a);
        float lo = to_tf32(a - hi);
        size_t o = ((size_t)(b * HW + hw0 + hh)) * CDIM + c0 + tx;
        g_Ahi[o] = hi;
        g_Alo[o] = lo;
    }
}

// ---------------------------------------------------------------------------
// Split codebook -> tf32 hi/lo (already (k, c) row-major)
// ---------------------------------------------------------------------------
__global__ void vq_split_cb(const float* __restrict__ cbk) {
    int i = blockIdx.x * 256 + threadIdx.x;
    float a  = cbk[i];
    float hi = to_tf32(a);
    float lo = to_tf32(a - hi);
    g_Bhi[i] = hi;
    g_Blo[i] = lo;
}

// ---------------------------------------------------------------------------
// Stage loader: chunk c (0..23) into pipeline slot s.
// chunk mapping: 0-7: Ahi*Bhi, 8-15: Alo*Bhi, 16-23: Ahi*Blo
// ---------------------------------------------------------------------------
__device__ __forceinline__ void load_stage(uint32_t sbu, int c, int s,
                                           int m0, int n0, int tid) {
    const float* Ap = (c < 8 || c >= 16) ? g_Ahi : g_Alo;
    const float* Bp = (c < 16) ? g_Bhi : g_Blo;
    int kb = (c & 7) * 32;
    uint32_t st = sbu + s * STAGE_BYTES;
    #pragma unroll
    for (int j = 0; j < 4; j++) {           // A: 128 rows x 128B
        int id = j * 256 + tid;
        int r = id >> 3, q = id & 7;
        cp_async16(st + SWZ(r * 128 + q * 16),
                   Ap + (size_t)(m0 + r) * CDIM + kb + q * 4);
    }
    #pragma unroll
    for (int j = 0; j < 4; j++) {           // B: 128 rows x 128B
        int id = j * 256 + tid;
        int r = id >> 3, q = id & 7;
        cp_async16(st + B_OFF + SWZ(r * 128 + q * 16),
                   Bp + (size_t)(n0 + r) * CDIM + kb + q * 4);
    }
}

// ---------------------------------------------------------------------------
// Main mma.sync tf32 GEMM + fused distance/argmin.
// Grid: 8192 CTAs = 128 m-tiles x 64 n-chunks. 256 threads (8 warps).
// Warp tile 64x32 (mma m16n8k8: 4 m-frags x 4 n-frags).
// ---------------------------------------------------------------------------
__global__ __launch_bounds__(256, 1) void vq_gemm() {
    extern __shared__ char smem_raw[];
    const uint32_t sbu = smem_u32(smem_raw);
    const int tid  = threadIdx.x;
    const int lane = tid & 31;
    const int wid  = tid >> 5;
    const int wm   = wid & 1;          // 2 m-blocks of 64
    const int wn   = wid >> 1;         // 4 n-blocks of 32
    const int gq   = lane >> 2;        // 0..7
    const int tq   = lane & 3;         // 0..3

    const int nt_blk = blockIdx.x & 63;
    const int mt_blk = blockIdx.x >> 6;
    const int m0 = mt_blk * MTILE;
    const int n0 = nt_blk * NTILE;

    // Swizzled col offsets within a 128B row: rxor = (row&7)<<4, and since all
    // fragment rows satisfy row&7 == gq, rxor is thread-constant.
    const uint32_t rxor = (uint32_t)gq << 4;
    uint32_t coff[8];
    #pragma unroll
    for (int ks = 0; ks < 4; ks++) {
        uint32_t base = ks * 32 + tq * 4;
        coff[2 * ks]     = base ^ rxor;
        coff[2 * ks + 1] = (base + 16) ^ rxor;
    }
    // Row byte offsets (relative to A / B tile base)
    uint32_t rA[4], rB[4];
    #pragma unroll
    for (int mt = 0; mt < 4; mt++) rA[mt] = (uint32_t)(wm * 64 + mt * 16 + gq) * 128;
    #pragma unroll
    for (int nt = 0; nt < 4; nt++) rB[nt] = (uint32_t)(wn * 32 + nt * 8 + gq) * 128;

    float acc[4][4][4];
    #pragma unroll
    for (int mt = 0; mt < 4; mt++)
        #pragma unroll
        for (int nt = 0; nt < 4; nt++)
            #pragma unroll
            for (int r = 0; r < 4; r++) acc[mt][nt][r] = 0.f;

    // Prologue: chunks 0..2 into slots 0..2
    #pragma unroll
    for (int s = 0; s < 3; s++) { load_stage(sbu, s, s, m0, n0, tid); CP_COMMIT(); }

    for (int c = 0; c < NKCH; c++) {
        asm volatile("cp.async.wait_group 2;" ::: "memory");
        __syncthreads();
        if (c + 3 < NKCH) load_stage(sbu, c + 3, (c + 3) & 3, m0, n0, tid);
        CP_COMMIT();

        const char* stA = smem_raw + (c & 3) * STAGE_BYTES;
        const char* stB = stA + B_OFF;
        #pragma unroll
        for (int ks = 0; ks < 4; ks++) {
            uint32_t a[4][4], b[4][2];
            #pragma unroll
            for (int mt = 0; mt < 4; mt++) {
                a[mt][0] = *(const uint32_t*)(stA + rA[mt] + coff[2 * ks]);
                a[mt][1] = *(const uint32_t*)(stA + rA[mt] + 1024 + coff[2 * ks]);
                a[mt][2] = *(const uint32_t*)(stA + rA[mt] + coff[2 * ks + 1]);
                a[mt][3] = *(const uint32_t*)(stA + rA[mt] + 1024 + coff[2 * ks + 1]);
            }
            #pragma unroll
            for (int nt = 0; nt < 4; nt++) {
                b[nt][0] = *(const uint32_t*)(stB + rB[nt] + coff[2 * ks]);
                b[nt][1] = *(const uint32_t*)(stB + rB[nt] + coff[2 * ks + 1]);
            }
            #pragma unroll
            for (int mt = 0; mt < 4; mt++)
                #pragma unroll
                for (int nt = 0; nt < 4; nt++)
                    mma_tf32(acc[mt][nt], a[mt], b[nt]);
        }
    }

    __syncthreads();   // done with stages; smem reused for reduction below

    // Epilogue: distances + argmin.
    // acc reg r: 0:(row gq, col 2tq) 1:(gq, 2tq+1) 2:(gq+8, 2tq) 3:(gq+8, 2tq+1)
    float* sval = (float*)smem_raw;            // [128][4]
    int*   sidx = (int*)(smem_raw + 2048);     // [128][4]

    #pragma unroll
    for (int mt = 0; mt < 4; mt++) {
        const int rl  = wm * 64 + mt * 16 + gq;
        const float zlo = g_zsq[m0 + rl];
        const float zhi = g_zsq[m0 + rl + 8];
        float bl = FLT_MAX, bh = FLT_MAX;
        int   il = 0, ih = 0;
        #pragma unroll
        for (int nt = 0; nt < 4; nt++) {
            const int nA = n0 + wn * 32 + nt * 8 + 2 * tq;
            const float e0 = __ldg(&g_esq[nA]);
            const float e1 = __ldg(&g_esq[nA + 1]);
            float d;
            d = fmaf(-2.0f, acc[mt][nt][0], zlo) + e0; if (d < bl) { bl = d; il = nA; }
            d = fmaf(-2.0f, acc[mt][nt][1], zlo) + e1; if (d < bl) { bl = d; il = nA + 1; }
            d = fmaf(-2.0f, acc[mt][nt][2], zhi) + e0; if (d < bh) { bh = d; ih = nA; }
            d = fmaf(-2.0f, acc[mt][nt][3], zhi) + e1; if (d < bh) { bh = d; ih = nA + 1; }
        }
        // reduce across the 4 lanes sharing each row (tq = 0..3)
        #pragma unroll
        for (int mask = 1; mask <= 2; mask <<= 1) {
            float ov; int oi;
            ov = __shfl_xor_sync(0xffffffffu, bl, mask);
            oi = __shfl_xor_sync(0xffffffffu, il, mask);
            if (ov < bl || (ov == bl && oi < il)) { bl = ov; il = oi; }
            ov = __shfl_xor_sync(0xffffffffu, bh, mask);
            oi = __shfl_xor_sync(0xffffffffu, ih, mask);
            if (ov < bh || (ov == bh && oi < ih)) { bh = ov; ih = oi; }
        }
        if (tq == 0) {
            sval[rl * 4 + wn]       = bl;  sidx[rl * 4 + wn]       = il;
            sval[(rl + 8) * 4 + wn] = bh;  sidx[(rl + 8) * 4 + wn] = ih;
        }
    }
    __syncthreads();

    if (tid < 128) {
        float best = sval[tid * 4];
        int   bi   = sidx[tid * 4];
        #pragma unroll
        for (int w = 1; w < 4; w++) {
            float v = sval[tid * 4 + w];
            int   i = sidx[tid * 4 + w];
            if (v < best || (v == best && i < bi)) { best = v; bi = i; }
        }
        g_pmin[(size_t)(m0 + tid) * NCHUNKS + nt_blk] = best;
        g_pidx[(size_t)(m0 + tid) * NCHUNKS + nt_blk] = bi;
    }
}

// ---------------------------------------------------------------------------
// Combine partial argmins (ascending chunk order => first-index tie-break)
// ---------------------------------------------------------------------------
__global__ void vq_combine(float* __restrict__ out_codes_f) {
    int row = blockIdx.x * 256 + threadIdx.x;
    const float* pm = g_pmin + (size_t)row * NCHUNKS;
    const int*   pi = g_pidx + (size_t)row * NCHUNKS;
    float best = pm[0];
    int   bi   = pi[0];
    #pragma unroll
    for (int t = 1; t < NCHUNKS; t++) {
        float v = pm[t];
        if (v < best) { best = v; bi = pi[t]; }
    }
    g_codes[row]     = bi;
    out_codes_f[row] = (float)bi;
}

// ---------------------------------------------------------------------------
// Gather quantized output (straight-through) + loss partials
// ---------------------------------------------------------------------------
__global__ void vq_gather_kernel(const float* __restrict__ z,
                                 const float* __restrict__ cbk,
                                 float* __restrict__ out_q) {
    __shared__ float sred[256];
    int o  = blockIdx.x * 256 + threadIdx.x;
    int hw = o & 1023;
    int c  = (o >> 10) & 255;
    int b  = o >> 18;
    int code = g_codes[(b << 10) + hw];
    float q  = __ldg(&cbk[(size_t)code * CDIM + c]);
    float zv = z[o];
    float qz = q - zv;
    out_q[o] = zv + qz;
    sred[threadIdx.x] = qz * qz;
    __syncthreads();
    #pragma unroll
    for (int off = 128; off > 0; off >>= 1) {
        if (threadIdx.x < off) sred[threadIdx.x] += sred[threadIdx.x + off];
        __syncthreads();
    }
    if (threadIdx.x == 0) g_partial[blockIdx.x] = sred[0];
}

__global__ void vq_finalize_kernel(float* __restrict__ out_loss) {
    __shared__ float s[256];
    float a = 0.f;
    for (int i = threadIdx.x; i < NELEM / 256; i += 256) a += g_partial[i];
    s[threadIdx.x] = a;
    __syncthreads();
    #pragma unroll
    for (int off = 128; off > 0; off >>= 1) {
        if (threadIdx.x < off) s[threadIdx.x] += s[threadIdx.x + off];
        __syncthreads();
    }
    if (threadIdx.x == 0)
        out_loss[0] = s[0] * (1.25f / (float)NELEM);
}

// ---------------------------------------------------------------------------
extern "C" void kernel_launch(void* const* d_in, const int* in_sizes, int n_in,
                              void* d_out, int out_size) {
    const float* z   = (const float*)d_in[0];   // (16,256,32,32) f32
    const float* cbk = (const float*)d_in[1];   // (8192,256) f32

    float* out       = (float*)d_out;
    float* out_codes = out;                     // 16384
    float* out_q     = out + NROWS;             // 4194304
    float* out_loss  = out + NROWS + NELEM;     // 1

    cudaFuncSetAttribute(vq_gemm, cudaFuncAttributeMaxDynamicSharedMemorySize,
                         SMEM_NEED);

    vq_esq_kernel<<<KCODES / 8, 256>>>(cbk);
    vq_zsq_kernel<<<NROWS / 256, 256>>>(z);
    vq_split_cb<<<(KCODES * CDIM) / 256, 256>>>(cbk);
    vq_split_z<<<dim3(HW / 32, CDIM / 32, BATCH), 256>>>(z);
    vq_gemm<<<(NROWS / MTILE) * (KCODES / NTILE), 256, SMEM_NEED>>>();
    vq_combine<<<NROWS / 256, 256>>>(out_codes);
    vq_gather_kernel<<<NELEM / 256, 256>>>(z, cbk, out_q);
    vq_finalize_kernel<<<1, 256>>>(out_loss);
}

// round 10
// speedup vs baseline: 3.0640x; 1.7538x over previous
#include <cuda_runtime.h>
#include <cuda_fp16.h>
#include <float.h>
#include <stdint.h>

// ---------------------------------------------------------------------------
// Problem constants
// ---------------------------------------------------------------------------
#define BATCH   16
#define CDIM    256
#define HW      1024
#define NROWS   16384          // BATCH*HW
#define KCODES  8192
#define NELEM   4194304        // BATCH*CDIM*HW

// GEMM config: fp16 3x split => K = 768 virtual halves, 12 chunks of 64
// chunk 0-3: Ahi*Bhi, 4-7: Alo*Bhi, 8-11: Ahi*Blo.  B pre-scaled by 2^12.
#define MTILE       128
#define NTILE       128
#define NCHUNKS     64         // 8192 / 128 n-chunks per row
#define NKCH        12
#define STAGES      4
#define STAGE_BYTES 32768      // A 16K + B 16K (128 rows x 128B, 64 halves)
#define B_OFF       16384
#define SMEM_NEED   (STAGES * STAGE_BYTES)   // 128 KB

// ---------------------------------------------------------------------------
// Device scratch (no cudaMalloc allowed)
// ---------------------------------------------------------------------------
__device__ __align__(16) __half g_Ahi[NROWS * CDIM];
__device__ __align__(16) __half g_Alo[NROWS * CDIM];
__device__ __align__(16) __half g_Bhi[KCODES * CDIM];
__device__ __align__(16) __half g_Blo[KCODES * CDIM];
__device__ float g_esq[KCODES];
__device__ float g_zsq[NROWS];
__device__ float g_pmin[NROWS * NCHUNKS];
__device__ int   g_pidx[NROWS * NCHUNKS];
__device__ int   g_codes[NROWS];
__device__ float g_partial[NELEM / 256];

// ---------------------------------------------------------------------------
// Helpers
// ---------------------------------------------------------------------------
__device__ __forceinline__ uint32_t smem_u32(const void* p) {
    uint32_t a;
    asm("{ .reg .u64 t; cvta.to.shared.u64 t, %1; cvt.u32.u64 %0, t; }"
        : "=r"(a) : "l"(p));
    return a;
}

// SW128-style swizzle (relative to tile base; 16B-granular)
#define SWZ(o) ((o) ^ (((o) >> 3) & 0x70))

__device__ __forceinline__ void cp_async16(uint32_t dst, const void* src) {
    asm volatile("cp.async.cg.shared.global [%0], [%1], 16;"
                 :: "r"(dst), "l"(src) : "memory");
}
#define CP_COMMIT() asm volatile("cp.async.commit_group;" ::: "memory")

__device__ __forceinline__ void mma_f16(float* c, const uint32_t* a,
                                        const uint32_t* b) {
    asm volatile(
        "mma.sync.aligned.m16n8k16.row.col.f32.f16.f16.f32 "
        "{%0,%1,%2,%3}, {%4,%5,%6,%7}, {%8,%9}, {%0,%1,%2,%3};"
        : "+f"(c[0]), "+f"(c[1]), "+f"(c[2]), "+f"(c[3])
        : "r"(a[0]), "r"(a[1]), "r"(a[2]), "r"(a[3]), "r"(b[0]), "r"(b[1]));
}

// ---------------------------------------------------------------------------
// e_sq[k] = sum_c codebook[k][c]^2   (original fp32 data)
// ---------------------------------------------------------------------------
__global__ void vq_esq_kernel(const float* __restrict__ cbk) {
    int k    = blockIdx.x * 8 + (threadIdx.x >> 5);
    int lane = threadIdx.x & 31;
    const float4* row = (const float4*)(cbk + (size_t)k * CDIM);
    float s = 0.f;
    #pragma unroll
    for (int i = lane; i < CDIM / 4; i += 32) {
        float4 v = row[i];
        s += v.x * v.x + v.y * v.y + v.z * v.z + v.w * v.w;
    }
    #pragma unroll
    for (int off = 16; off > 0; off >>= 1)
        s += __shfl_down_sync(0xffffffffu, s, off);
    if (lane == 0) g_esq[k] = s;
}

// ---------------------------------------------------------------------------
// z_sq[n] = sum_c z[b][c][hw]^2
// ---------------------------------------------------------------------------
__global__ void vq_zsq_kernel(const float* __restrict__ z) {
    int n  = blockIdx.x * 256 + threadIdx.x;
    int b  = n >> 10;
    int hw = n & 1023;
    const float* p = z + (size_t)b * CDIM * HW + hw;
    float s = 0.f;
    #pragma unroll 8
    for (int c = 0; c < CDIM; c++) {
        float v = p[(size_t)c * HW];
        s += v * v;
    }
    g_zsq[n] = s;
}

// ---------------------------------------------------------------------------
// Split z -> fp16 hi/lo, transposed to row-major (n, c), via SMEM transpose
// ---------------------------------------------------------------------------
__global__ void vq_split_z(const float* __restrict__ z) {
    __shared__ float t[32][33];
    int b   = blockIdx.z;
    int c0  = blockIdx.y * 32;
    int hw0 = blockIdx.x * 32;
    int tx  = threadIdx.x & 31;
    int ty  = threadIdx.x >> 5;        // 0..7
    const float* src = z + ((size_t)b * CDIM + c0) * HW + hw0;
    #pragma unroll
    for (int j = 0; j < 4; j++) {
        int c = ty + j * 8;
        t[c][tx] = src[(size_t)c * HW + tx];
    }
    __syncthreads();
    #pragma unroll
    for (int j = 0; j < 4; j++) {
        int hh = ty + j * 8;
        float a  = t[tx][hh];
        __half hi = __float2half_rn(a);
        __half lo = __float2half_rn(a - __half2float(hi));
        size_t o = ((size_t)(b * HW + hw0 + hh)) * CDIM + c0 + tx;
        g_Ahi[o] = hi;
        g_Alo[o] = lo;
    }
}

// ---------------------------------------------------------------------------
// Split codebook -> fp16 hi/lo, pre-scaled by 2^12 (exact) to keep lo parts
// well inside fp16 normal range.
// ---------------------------------------------------------------------------
__global__ void vq_split_cb(const float* __restrict__ cbk) {
    int i = blockIdx.x * 256 + threadIdx.x;
    float a  = cbk[i] * 4096.0f;            // exact power-of-two scale
    __half hi = __float2half_rn(a);
    __half lo = __float2half_rn(a - __half2float(hi));
    g_Bhi[i] = hi;
    g_Blo[i] = lo;
}

// ---------------------------------------------------------------------------
// Stage loader: chunk c (0..11) into pipeline slot s.
// Tile: 128 rows x 64 halves (128B rows), A then B.
// ---------------------------------------------------------------------------
__device__ __forceinline__ void load_stage(uint32_t sbu, int c, int s,
                                           int m0, int n0, int tid) {
    const __half* Ap = (c < 4 || c >= 8) ? g_Ahi : g_Alo;
    const __half* Bp = (c < 8) ? g_Bhi : g_Blo;
    int kb = (c & 3) * 64;                  // halves
    uint32_t st = sbu + s * STAGE_BYTES;
    #pragma unroll
    for (int j = 0; j < 4; j++) {           // A: 128 rows x 128B
        int id = j * 256 + tid;
        int r = id >> 3, q = id & 7;
        cp_async16(st + SWZ(r * 128 + q * 16),
                   Ap + (size_t)(m0 + r) * CDIM + kb + q * 8);
    }
    #pragma unroll
    for (int j = 0; j < 4; j++) {           // B: 128 rows x 128B
        int id = j * 256 + tid;
        int r = id >> 3, q = id & 7;
        cp_async16(st + B_OFF + SWZ(r * 128 + q * 16),
                   Bp + (size_t)(n0 + r) * CDIM + kb + q * 8);
    }
}

// ---------------------------------------------------------------------------
// Main mma.sync fp16 GEMM + fused distance/argmin.
// Grid: 8192 CTAs = 128 m-tiles x 64 n-chunks. 256 threads (8 warps).
// Warp tile 64x32 (mma m16n8k16: 4 m-frags x 4 n-frags).
// ---------------------------------------------------------------------------
__global__ __launch_bounds__(256, 1) void vq_gemm() {
    extern __shared__ char smem_raw[];
    const uint32_t sbu = smem_u32(smem_raw);
    const int tid  = threadIdx.x;
    const int lane = tid & 31;
    const int wid  = tid >> 5;
    const int wm   = wid & 1;          // 2 m-blocks of 64
    const int wn   = wid >> 1;         // 4 n-blocks of 32
    const int gq   = lane >> 2;        // 0..7
    const int tq   = lane & 3;         // 0..3

    const int nt_blk = blockIdx.x & 63;
    const int mt_blk = blockIdx.x >> 6;
    const int m0 = mt_blk * MTILE;
    const int n0 = nt_blk * NTILE;

    // Swizzled col offsets: all fragment rows satisfy row&7 == gq.
    const uint32_t rxor = (uint32_t)gq << 4;
    uint32_t coff[8];
    #pragma unroll
    for (int ks = 0; ks < 4; ks++) {
        uint32_t base = ks * 32 + tq * 4;          // bytes: k-pair 2tq of step ks
        coff[2 * ks]     = base ^ rxor;            // k = ks*16 + 2tq
        coff[2 * ks + 1] = (base + 16) ^ rxor;     // k = ks*16 + 2tq + 8
    }
    uint32_t rA[4], rB[4];
    #pragma unroll
    for (int mt = 0; mt < 4; mt++) rA[mt] = (uint32_t)(wm * 64 + mt * 16 + gq) * 128;
    #pragma unroll
    for (int nt = 0; nt < 4; nt++) rB[nt] = (uint32_t)(wn * 32 + nt * 8 + gq) * 128;

    float acc[4][4][4];
    #pragma unroll
    for (int mt = 0; mt < 4; mt++)
        #pragma unroll
        for (int nt = 0; nt < 4; nt++)
            #pragma unroll
            for (int r = 0; r < 4; r++) acc[mt][nt][r] = 0.f;

    // Prologue: chunks 0..2 into slots 0..2
    #pragma unroll
    for (int s = 0; s < 3; s++) { load_stage(sbu, s, s, m0, n0, tid); CP_COMMIT(); }

    for (int c = 0; c < NKCH; c++) {
        asm volatile("cp.async.wait_group 2;" ::: "memory");
        __syncthreads();
        if (c + 3 < NKCH) load_stage(sbu, c + 3, (c + 3) & 3, m0, n0, tid);
        CP_COMMIT();

        const char* stA = smem_raw + (c & 3) * STAGE_BYTES;
        const char* stB = stA + B_OFF;
        #pragma unroll
        for (int ks = 0; ks < 4; ks++) {
            uint32_t a[4][4], b[4][2];
            #pragma unroll
            for (int mt = 0; mt < 4; mt++) {
                // a0:(gq,k0..1) a1:(gq+8,k0..1) a2:(gq,k8..9) a3:(gq+8,k8..9)
                a[mt][0] = *(const uint32_t*)(stA + rA[mt] + coff[2 * ks]);
                a[mt][1] = *(const uint32_t*)(stA + rA[mt] + 1024 + coff[2 * ks]);
                a[mt][2] = *(const uint32_t*)(stA + rA[mt] + coff[2 * ks + 1]);
                a[mt][3] = *(const uint32_t*)(stA + rA[mt] + 1024 + coff[2 * ks + 1]);
            }
            #pragma unroll
            for (int nt = 0; nt < 4; nt++) {
                b[nt][0] = *(const uint32_t*)(stB + rB[nt] + coff[2 * ks]);
                b[nt][1] = *(const uint32_t*)(stB + rB[nt] + coff[2 * ks + 1]);
            }
            #pragma unroll
            for (int mt = 0; mt < 4; mt++)
                #pragma unroll
                for (int nt = 0; nt < 4; nt++)
                    mma_f16(acc[mt][nt], a[mt], b[nt]);
        }
    }

    __syncthreads();   // stages done; smem reused for reduction

    // Epilogue: unscale (exact *2^-12), distances, argmin.
    // acc reg r: 0:(row gq, col 2tq) 1:(gq, 2tq+1) 2:(gq+8, 2tq) 3:(gq+8, 2tq+1)
    float* sval = (float*)smem_raw;            // [128][4]
    int*   sidx = (int*)(smem_raw + 2048);     // [128][4]

    #pragma unroll
    for (int mt = 0; mt < 4; mt++) {
        const int rl  = wm * 64 + mt * 16 + gq;
        const float zlo = g_zsq[m0 + rl];
        const float zhi = g_zsq[m0 + rl + 8];
        float bl = FLT_MAX, bh = FLT_MAX;
        int   il = 0, ih = 0;
        #pragma unroll
        for (int nt = 0; nt < 4; nt++) {
            const int nA = n0 + wn * 32 + nt * 8 + 2 * tq;
            const float e0 = __ldg(&g_esq[nA]);
            const float e1 = __ldg(&g_esq[nA + 1]);
            float d;
            d = fmaf(-0x1p-11f, acc[mt][nt][0], zlo) + e0; if (d < bl) { bl = d; il = nA; }
            d = fmaf(-0x1p-11f, acc[mt][nt][1], zlo) + e1; if (d < bl) { bl = d; il = nA + 1; }
            d = fmaf(-0x1p-11f, acc[mt][nt][2], zhi) + e0; if (d < bh) { bh = d; ih = nA; }
            d = fmaf(-0x1p-11f, acc[mt][nt][3], zhi) + e1; if (d < bh) { bh = d; ih = nA + 1; }
        }
        #pragma unroll
        for (int mask = 1; mask <= 2; mask <<= 1) {
            float ov; int oi;
            ov = __shfl_xor_sync(0xffffffffu, bl, mask);
            oi = __shfl_xor_sync(0xffffffffu, il, mask);
            if (ov < bl || (ov == bl && oi < il)) { bl = ov; il = oi; }
            ov = __shfl_xor_sync(0xffffffffu, bh, mask);
            oi = __shfl_xor_sync(0xffffffffu, ih, mask);
            if (ov < bh || (ov == bh && oi < ih)) { bh = ov; ih = oi; }
        }
        if (tq == 0) {
            sval[rl * 4 + wn]       = bl;  sidx[rl * 4 + wn]       = il;
            sval[(rl + 8) * 4 + wn] = bh;  sidx[(rl + 8) * 4 + wn] = ih;
        }
    }
    __syncthreads();

    if (tid < 128) {
        float best = sval[tid * 4];
        int   bi   = sidx[tid * 4];
        #pragma unroll
        for (int w = 1; w < 4; w++) {
            float v = sval[tid * 4 + w];
            int   i = sidx[tid * 4 + w];
            if (v < best || (v == best && i < bi)) { best = v; bi = i; }
        }
        g_pmin[(size_t)(m0 + tid) * NCHUNKS + nt_blk] = best;
        g_pidx[(size_t)(m0 + tid) * NCHUNKS + nt_blk] = bi;
    }
}

// ---------------------------------------------------------------------------
// Combine partial argmins (ascending chunk order => first-index tie-break)
// ---------------------------------------------------------------------------
__global__ void vq_combine(float* __restrict__ out_codes_f) {
    int row = blockIdx.x * 256 + threadIdx.x;
    const float* pm = g_pmin + (size_t)row * NCHUNKS;
    const int*   pi = g_pidx + (size_t)row * NCHUNKS;
    float best = pm[0];
    int   bi   = pi[0];
    #pragma unroll
    for (int t = 1; t < NCHUNKS; t++) {
        float v = pm[t];
        if (v < best) { best = v; bi = pi[t]; }
    }
    g_codes[row]     = bi;
    out_codes_f[row] = (float)bi;
}

// ---------------------------------------------------------------------------
// Gather quantized output (straight-through) + loss partials
// ---------------------------------------------------------------------------
__global__ void vq_gather_kernel(const float* __restrict__ z,
                                 const float* __restrict__ cbk,
                                 float* __restrict__ out_q) {
    __shared__ float sred[256];
    int o  = blockIdx.x * 256 + threadIdx.x;
    int hw = o & 1023;
    int c  = (o >> 10) & 255;
    int b  = o >> 18;
    int code = g_codes[(b << 10) + hw];
    float q  = __ldg(&cbk[(size_t)code * CDIM + c]);
    float zv = z[o];
    float qz = q - zv;
    out_q[o] = zv + qz;
    sred[threadIdx.x] = qz * qz;
    __syncthreads();
    #pragma unroll
    for (int off = 128; off > 0; off >>= 1) {
        if (threadIdx.x < off) sred[threadIdx.x] += sred[threadIdx.x + off];
        __syncthreads();
    }
    if (threadIdx.x == 0) g_partial[blockIdx.x] = sred[0];
}

__global__ void vq_finalize_kernel(float* __restrict__ out_loss) {
    __shared__ float s[256];
    float a = 0.f;
    for (int i = threadIdx.x; i < NELEM / 256; i += 256) a += g_partial[i];
    s[threadIdx.x] = a;
    __syncthreads();
    #pragma unroll
    for (int off = 128; off > 0; off >>= 1) {
        if (threadIdx.x < off) s[threadIdx.x] += s[threadIdx.x + off];
        __syncthreads();
    }
    if (threadIdx.x == 0)
        out_loss[0] = s[0] * (1.25f / (float)NELEM);
}

// ---------------------------------------------------------------------------
extern "C" void kernel_launch(void* const* d_in, const int* in_sizes, int n_in,
                              void* d_out, int out_size) {
    const float* z   = (const float*)d_in[0];   // (16,256,32,32) f32
    const float* cbk = (const float*)d_in[1];   // (8192,256) f32

    float* out       = (float*)d_out;
    float* out_codes = out;                     // 16384
    float* out_q     = out + NROWS;             // 4194304
    float* out_loss  = out + NROWS + NELEM;     // 1

    cudaFuncSetAttribute(vq_gemm, cudaFuncAttributeMaxDynamicSharedMemorySize,
                         SMEM_NEED);

    vq_esq_kernel<<<KCODES / 8, 256>>>(cbk);
    vq_zsq_kernel<<<NROWS / 256, 256>>>(z);
    vq_split_cb<<<(KCODES * CDIM) / 256, 256>>>(cbk);
    vq_split_z<<<dim3(HW / 32, CDIM / 32, BATCH), 256>>>(z);
    vq_gemm<<<(NROWS / MTILE) * (KCODES / NTILE), 256, SMEM_NEED>>>();
    vq_combine<<<NROWS / 256, 256>>>(out_codes);
    vq_gather_kernel<<<NELEM / 256, 256>>>(z, cbk, out_q);
    vq_finalize_kernel<<<1, 256>>>(out_loss);
}

// round 11
// speedup vs baseline: 3.6427x; 1.1889x over previous
#include <cuda_runtime.h>
#include <cuda_fp16.h>
#include <float.h>
#include <stdint.h>

// ---------------------------------------------------------------------------
// Problem constants
// ---------------------------------------------------------------------------
#define BATCH   16
#define CDIM    256
#define HW      1024
#define NROWS   16384          // BATCH*HW
#define KCODES  8192
#define NELEM   4194304        // BATCH*CDIM*HW

// GEMM config: fp16 3x split => K = 768 virtual halves, 12 chunks of 64
// chunk 0-3: Ahi*Bhi, 4-7: Alo*Bhi, 8-11: Ahi*Blo.  B pre-scaled by 2^12.
// CTA tile 256x128, 8 warps of 64x64 (m16n8k16: 4 m-frags x 8 n-frags).
#define MTILE       256
#define NTILE       128
#define NCHUNKS     64         // 8192 / 128 n-chunks per row
#define NKCH        12
#define STAGES      4
#define STAGE_BYTES 49152      // A 32K (256 rows x 128B) + B 16K (128 x 128B)
#define B_OFF       32768
#define SMEM_NEED   (STAGES * STAGE_BYTES)   // 192 KB

// ---------------------------------------------------------------------------
// Device scratch (no cudaMalloc allowed)
// ---------------------------------------------------------------------------
__device__ __align__(16) __half g_Ahi[NROWS * CDIM];
__device__ __align__(16) __half g_Alo[NROWS * CDIM];
__device__ __align__(16) __half g_Bhi[KCODES * CDIM];
__device__ __align__(16) __half g_Blo[KCODES * CDIM];
__device__ float g_esq[KCODES];
__device__ float g_zsq[NROWS];
__device__ float g_pmin[NROWS * NCHUNKS];
__device__ int   g_pidx[NROWS * NCHUNKS];
__device__ int   g_codes[NROWS];
__device__ float g_partial[2048];

// ---------------------------------------------------------------------------
// Helpers
// ---------------------------------------------------------------------------
__device__ __forceinline__ uint32_t smem_u32(const void* p) {
    uint32_t a;
    asm("{ .reg .u64 t; cvta.to.shared.u64 t, %1; cvt.u32.u64 %0, t; }"
        : "=r"(a) : "l"(p));
    return a;
}

// SW128-style swizzle (relative to tile base; 16B-granular)
#define SWZ(o) ((o) ^ (((o) >> 3) & 0x70))

__device__ __forceinline__ void cp_async16(uint32_t dst, const void* src) {
    asm volatile("cp.async.cg.shared.global [%0], [%1], 16;"
                 :: "r"(dst), "l"(src) : "memory");
}
#define CP_COMMIT() asm volatile("cp.async.commit_group;" ::: "memory")

__device__ __forceinline__ void mma_f16(float* c, const uint32_t* a,
                                        const uint32_t* b) {
    asm volatile(
        "mma.sync.aligned.m16n8k16.row.col.f32.f16.f16.f32 "
        "{%0,%1,%2,%3}, {%4,%5,%6,%7}, {%8,%9}, {%0,%1,%2,%3};"
        : "+f"(c[0]), "+f"(c[1]), "+f"(c[2]), "+f"(c[3])
        : "r"(a[0]), "r"(a[1]), "r"(a[2]), "r"(a[3]), "r"(b[0]), "r"(b[1]));
}

// ---------------------------------------------------------------------------
// e_sq[k] = sum_c codebook[k][c]^2   (original fp32 data)
// ---------------------------------------------------------------------------
__global__ void vq_esq_kernel(const float* __restrict__ cbk) {
    int k    = blockIdx.x * 8 + (threadIdx.x >> 5);
    int lane = threadIdx.x & 31;
    const float4* row = (const float4*)(cbk + (size_t)k * CDIM);
    float s = 0.f;
    #pragma unroll
    for (int i = lane; i < CDIM / 4; i += 32) {
        float4 v = row[i];
        s += v.x * v.x + v.y * v.y + v.z * v.z + v.w * v.w;
    }
    #pragma unroll
    for (int off = 16; off > 0; off >>= 1)
        s += __shfl_down_sync(0xffffffffu, s, off);
    if (lane == 0) g_esq[k] = s;
}

// ---------------------------------------------------------------------------
// z_sq[n] = sum_c z[b][c][hw]^2
// ---------------------------------------------------------------------------
__global__ void vq_zsq_kernel(const float* __restrict__ z) {
    int n  = blockIdx.x * 256 + threadIdx.x;
    int b  = n >> 10;
    int hw = n & 1023;
    const float* p = z + (size_t)b * CDIM * HW + hw;
    float s = 0.f;
    #pragma unroll 8
    for (int c = 0; c < CDIM; c++) {
        float v = p[(size_t)c * HW];
        s += v * v;
    }
    g_zsq[n] = s;
}

// ---------------------------------------------------------------------------
// Split z -> fp16 hi/lo, transposed to row-major (n, c), via SMEM transpose
// ---------------------------------------------------------------------------
__global__ void vq_split_z(const float* __restrict__ z) {
    __shared__ float t[32][33];
    int b   = blockIdx.z;
    int c0  = blockIdx.y * 32;
    int hw0 = blockIdx.x * 32;
    int tx  = threadIdx.x & 31;
    int ty  = threadIdx.x >> 5;        // 0..7
    const float* src = z + ((size_t)b * CDIM + c0) * HW + hw0;
    #pragma unroll
    for (int j = 0; j < 4; j++) {
        int c = ty + j * 8;
        t[c][tx] = src[(size_t)c * HW + tx];
    }
    __syncthreads();
    #pragma unroll
    for (int j = 0; j < 4; j++) {
        int hh = ty + j * 8;
        float a  = t[tx][hh];
        __half hi = __float2half_rn(a);
        __half lo = __float2half_rn(a - __half2float(hi));
        size_t o = ((size_t)(b * HW + hw0 + hh)) * CDIM + c0 + tx;
        g_Ahi[o] = hi;
        g_Alo[o] = lo;
    }
}

// ---------------------------------------------------------------------------
// Split codebook -> fp16 hi/lo, pre-scaled by 2^12 (exact power of two)
// ---------------------------------------------------------------------------
__global__ void vq_split_cb(const float* __restrict__ cbk) {
    int i = blockIdx.x * 256 + threadIdx.x;
    float a  = cbk[i] * 4096.0f;
    __half hi = __float2half_rn(a);
    __half lo = __float2half_rn(a - __half2float(hi));
    g_Bhi[i] = hi;
    g_Blo[i] = lo;
}

// ---------------------------------------------------------------------------
// Stage loader: chunk c (0..11) into pipeline slot s.
// A: 256 rows x 128B (64 halves); B: 128 rows x 128B.
// ---------------------------------------------------------------------------
__device__ __forceinline__ void load_stage(uint32_t sbu, int c, int s,
                                           int m0, int n0, int tid) {
    const __half* Ap = (c < 4 || c >= 8) ? g_Ahi : g_Alo;
    const __half* Bp = (c < 8) ? g_Bhi : g_Blo;
    int kb = (c & 3) * 64;                  // halves
    uint32_t st = sbu + s * STAGE_BYTES;
    #pragma unroll
    for (int j = 0; j < 8; j++) {           // A: 2048 cp16
        int id = j * 256 + tid;
        int r = id >> 3, q = id & 7;
        cp_async16(st + SWZ(r * 128 + q * 16),
                   Ap + (size_t)(m0 + r) * CDIM + kb + q * 8);
    }
    #pragma unroll
    for (int j = 0; j < 4; j++) {           // B: 1024 cp16
        int id = j * 256 + tid;
        int r = id >> 3, q = id & 7;
        cp_async16(st + B_OFF + SWZ(r * 128 + q * 16),
                   Bp + (size_t)(n0 + r) * CDIM + kb + q * 8);
    }
}

// ---------------------------------------------------------------------------
// Main mma.sync fp16 GEMM + fused distance/argmin.
// Grid: 4096 CTAs = 64 m-tiles (256 rows) x 64 n-chunks (128 codes).
// 8 warps, warp tile 64x64: wm = wid&3 (m-block of 64), wn = wid>>2.
// ---------------------------------------------------------------------------
__global__ __launch_bounds__(256, 1) void vq_gemm() {
    extern __shared__ char smem_raw[];
    const uint32_t sbu = smem_u32(smem_raw);
    const int tid  = threadIdx.x;
    const int lane = tid & 31;
    const int wid  = tid >> 5;
    const int wm   = wid & 3;          // 4 m-blocks of 64
    const int wn   = wid >> 2;         // 2 n-blocks of 64
    const int gq   = lane >> 2;        // 0..7
    const int tq   = lane & 3;         // 0..3

    const int nt_blk = blockIdx.x & 63;
    const int mt_blk = blockIdx.x >> 6;
    const int m0 = mt_blk * MTILE;
    const int n0 = nt_blk * NTILE;

    // Swizzled col offsets: all fragment rows satisfy row&7 == gq.
    const uint32_t rxor = (uint32_t)gq << 4;
    uint32_t coff[8];
    #pragma unroll
    for (int ks = 0; ks < 4; ks++) {
        uint32_t base = ks * 32 + tq * 4;
        coff[2 * ks]     = base ^ rxor;            // k = ks*16 + 2tq
        coff[2 * ks + 1] = (base + 16) ^ rxor;     // k = ks*16 + 2tq + 8
    }
    uint32_t rA[4], rB[8];
    #pragma unroll
    for (int mt = 0; mt < 4; mt++) rA[mt] = (uint32_t)(wm * 64 + mt * 16 + gq) * 128;
    #pragma unroll
    for (int nt = 0; nt < 8; nt++) rB[nt] = (uint32_t)(wn * 64 + nt * 8 + gq) * 128;

    float acc[4][8][4];
    #pragma unroll
    for (int mt = 0; mt < 4; mt++)
        #pragma unroll
        for (int nt = 0; nt < 8; nt++)
            #pragma unroll
            for (int r = 0; r < 4; r++) acc[mt][nt][r] = 0.f;

    // Prologue: chunks 0..2 into slots 0..2
    #pragma unroll
    for (int s = 0; s < 3; s++) { load_stage(sbu, s, s, m0, n0, tid); CP_COMMIT(); }

    for (int c = 0; c < NKCH; c++) {
        // chunk c must be resident before compute (proper tail ladder)
        if (c < NKCH - 2)       asm volatile("cp.async.wait_group 2;" ::: "memory");
        else if (c == NKCH - 2) asm volatile("cp.async.wait_group 1;" ::: "memory");
        else                    asm volatile("cp.async.wait_group 0;" ::: "memory");
        __syncthreads();
        if (c + 3 < NKCH) { load_stage(sbu, c + 3, (c + 3) & 3, m0, n0, tid); CP_COMMIT(); }

        const char* stA = smem_raw + (c & 3) * STAGE_BYTES;
        const char* stB = stA + B_OFF;
        #pragma unroll
        for (int ks = 0; ks < 4; ks++) {
            uint32_t a[4][4], b[8][2];
            #pragma unroll
            for (int mt = 0; mt < 4; mt++) {
                a[mt][0] = *(const uint32_t*)(stA + rA[mt] + coff[2 * ks]);
                a[mt][1] = *(const uint32_t*)(stA + rA[mt] + 1024 + coff[2 * ks]);
                a[mt][2] = *(const uint32_t*)(stA + rA[mt] + coff[2 * ks + 1]);
                a[mt][3] = *(const uint32_t*)(stA + rA[mt] + 1024 + coff[2 * ks + 1]);
            }
            #pragma unroll
            for (int nt = 0; nt < 8; nt++) {
                b[nt][0] = *(const uint32_t*)(stB + rB[nt] + coff[2 * ks]);
                b[nt][1] = *(const uint32_t*)(stB + rB[nt] + coff[2 * ks + 1]);
            }
            #pragma unroll
            for (int mt = 0; mt < 4; mt++)
                #pragma unroll
                for (int nt = 0; nt < 8; nt++)
                    mma_f16(acc[mt][nt], a[mt], b[nt]);
        }
    }

    __syncthreads();   // stages done; smem reused for reduction

    // Epilogue: unscale (exact *2^-12 folded into the -2 factor), distances,
    // argmin.  acc r: 0:(gq,2tq) 1:(gq,2tq+1) 2:(gq+8,2tq) 3:(gq+8,2tq+1)
    float* sval = (float*)smem_raw;            // [256][2]
    int*   sidx = (int*)(smem_raw + 2048);     // [256][2]

    #pragma unroll
    for (int mt = 0; mt < 4; mt++) {
        const int rl  = wm * 64 + mt * 16 + gq;
        const float zlo = g_zsq[m0 + rl];
        const float zhi = g_zsq[m0 + rl + 8];
        float bl = FLT_MAX, bh = FLT_MAX;
        int   il = 0, ih = 0;
        #pragma unroll
        for (int nt = 0; nt < 8; nt++) {
            const int nA = n0 + wn * 64 + nt * 8 + 2 * tq;
            const float e0 = __ldg(&g_esq[nA]);
            const float e1 = __ldg(&g_esq[nA + 1]);
            float d;
            d = fmaf(-0x1p-11f, acc[mt][nt][0], zlo) + e0; if (d < bl) { bl = d; il = nA; }
            d = fmaf(-0x1p-11f, acc[mt][nt][1], zlo) + e1; if (d < bl) { bl = d; il = nA + 1; }
            d = fmaf(-0x1p-11f, acc[mt][nt][2], zhi) + e0; if (d < bh) { bh = d; ih = nA; }
            d = fmaf(-0x1p-11f, acc[mt][nt][3], zhi) + e1; if (d < bh) { bh = d; ih = nA + 1; }
        }
        #pragma unroll
        for (int mask = 1; mask <= 2; mask <<= 1) {
            float ov; int oi;
            ov = __shfl_xor_sync(0xffffffffu, bl, mask);
            oi = __shfl_xor_sync(0xffffffffu, il, mask);
            if (ov < bl || (ov == bl && oi < il)) { bl = ov; il = oi; }
            ov = __shfl_xor_sync(0xffffffffu, bh, mask);
            oi = __shfl_xor_sync(0xffffffffu, ih, mask);
            if (ov < bh || (ov == bh && oi < ih)) { bh = ov; ih = oi; }
        }
        if (tq == 0) {
            sval[rl * 2 + wn]       = bl;  sidx[rl * 2 + wn]       = il;
            sval[(rl + 8) * 2 + wn] = bh;  sidx[(rl + 8) * 2 + wn] = ih;
        }
    }
    __syncthreads();

    {   // 256 threads: one row each, combine the 2 n-halves (index tie-break)
        float best = sval[tid * 2];
        int   bi   = sidx[tid * 2];
        float v = sval[tid * 2 + 1];
        int   i = sidx[tid * 2 + 1];
        if (v < best || (v == best && i < bi)) { best = v; bi = i; }
        g_pmin[(size_t)(m0 + tid) * NCHUNKS + nt_blk] = best;
        g_pidx[(size_t)(m0 + tid) * NCHUNKS + nt_blk] = bi;
    }
}

// ---------------------------------------------------------------------------
// Combine partial argmins (ascending chunk order => first-index tie-break)
// ---------------------------------------------------------------------------
__global__ void vq_combine(float* __restrict__ out_codes_f) {
    int row = blockIdx.x * 256 + threadIdx.x;
    const float* pm = g_pmin + (size_t)row * NCHUNKS;
    const int*   pi = g_pidx + (size_t)row * NCHUNKS;
    float best = pm[0];
    int   bi   = pi[0];
    #pragma unroll
    for (int t = 1; t < NCHUNKS; t++) {
        float v = pm[t];
        if (v < best) { best = v; bi = pi[t]; }
    }
    g_codes[row]     = bi;
    out_codes_f[row] = (float)bi;
}

// ---------------------------------------------------------------------------
// Gather quantized output (straight-through) + loss partials.
// float4 vectorized, grid-stride (2 f4 per thread), one block-reduce.
// ---------------------------------------------------------------------------
__global__ void vq_gather_kernel(const float* __restrict__ z,
                                 const float* __restrict__ cbk,
                                 float* __restrict__ out_q) {
    __shared__ float sred[256];
    const float4* z4 = (const float4*)z;
    float4* q4 = (float4*)out_q;
    float accum = 0.f;
    #pragma unroll
    for (int j = 0; j < 2; j++) {
        int i = j * 524288 + blockIdx.x * 256 + threadIdx.x;   // f4 index
        int e  = i << 2;                 // element index
        int hw = e & 1023;
        int c  = (e >> 10) & 255;
        int b  = e >> 18;
        const int* cd = &g_codes[(b << 10) + hw];
        float4 zv = z4[i];
        float4 qv;
        qv.x = __ldg(&cbk[(size_t)cd[0] * CDIM + c]);
        qv.y = __ldg(&cbk[(size_t)cd[1] * CDIM + c]);
        qv.z = __ldg(&cbk[(size_t)cd[2] * CDIM + c]);
        qv.w = __ldg(&cbk[(size_t)cd[3] * CDIM + c]);
        float dx = qv.x - zv.x, dy = qv.y - zv.y;
        float dz = qv.z - zv.z, dw = qv.w - zv.w;
        float4 o;
        o.x = zv.x + dx; o.y = zv.y + dy; o.z = zv.z + dz; o.w = zv.w + dw;
        q4[i] = o;
        accum += dx * dx + dy * dy + dz * dz + dw * dw;
    }
    sred[threadIdx.x] = accum;
    __syncthreads();
    #pragma unroll
    for (int off = 128; off > 0; off >>= 1) {
        if (threadIdx.x < off) sred[threadIdx.x] += sred[threadIdx.x + off];
        __syncthreads();
    }
    if (threadIdx.x == 0) g_partial[blockIdx.x] = sred[0];
}

__global__ void vq_finalize_kernel(float* __restrict__ out_loss) {
    __shared__ float s[256];
    float a = 0.f;
    for (int i = threadIdx.x; i < 2048; i += 256) a += g_partial[i];
    s[threadIdx.x] = a;
    __syncthreads();
    #pragma unroll
    for (int off = 128; off > 0; off >>= 1) {
        if (threadIdx.x < off) s[threadIdx.x] += s[threadIdx.x + off];
        __syncthreads();
    }
    if (threadIdx.x == 0)
        out_loss[0] = s[0] * (1.25f / (float)NELEM);
}

// ---------------------------------------------------------------------------
extern "C" void kernel_launch(void* const* d_in, const int* in_sizes, int n_in,
                              void* d_out, int out_size) {
    const float* z   = (const float*)d_in[0];   // (16,256,32,32) f32
    const float* cbk = (const float*)d_in[1];   // (8192,256) f32

    float* out       = (float*)d_out;
    float* out_codes = out;                     // 16384
    float* out_q     = out + NROWS;             // 4194304
    float* out_loss  = out + NROWS + NELEM;     // 1

    cudaFuncSetAttribute(vq_gemm, cudaFuncAttributeMaxDynamicSharedMemorySize,
                         SMEM_NEED);

    vq_esq_kernel<<<KCODES / 8, 256>>>(cbk);
    vq_zsq_kernel<<<NROWS / 256, 256>>>(z);
    vq_split_cb<<<(KCODES * CDIM) / 256, 256>>>(cbk);
    vq_split_z<<<dim3(HW / 32, CDIM / 32, BATCH), 256>>>(z);
    vq_gemm<<<(NROWS / MTILE) * (KCODES / NTILE), 256, SMEM_NEED>>>();
    vq_combine<<<NROWS / 256, 256>>>(out_codes);
    vq_gather_kernel<<<2048, 256>>>(z, cbk, out_q);
    vq_finalize_kernel<<<1, 256>>>(out_loss);
}